// round 6
// baseline (speedup 1.0000x reference)
#include <cuda_runtime.h>
#include <cuda_bf16.h>
#include <math.h>
#include <stdint.h>

#define N_NODES 50000
#define E_EDGES 800000
#define DIN 256
#define DH 128
#define DOUT 64

// ---------------- scratch (static device globals; no allocation) ----------------
__device__ __nv_bfloat16 g_xb[(size_t)N_NODES * DIN]; // x converted to bf16
__device__ __nv_bfloat16 g_h[(size_t)N_NODES * DH];   // GEMM out / agg gather in (bf16)
__device__ __nv_bfloat16 g_a[(size_t)N_NODES * DH];   // agg out / GEMM in (bf16)
__device__ __nv_bfloat16 g_w0[DIN * DH];
__device__ __nv_bfloat16 g_w1[DH * DH];
__device__ __nv_bfloat16 g_w2[DH * DOUT];
__device__ float g_dinv[N_NODES];
__device__ int   g_deg[N_NODES];
__device__ int   g_offs[N_NODES + 1];
__device__ int   g_cursor[N_NODES];
__device__ int2  g_edge[E_EDGES];               // .x = src, .y = float bits of norm
__device__ unsigned long long g_state[64];      // decoupled-lookback state

// ---------------- conversions ----------------
__global__ void k_cvt(const float* __restrict__ src, __nv_bfloat16* __restrict__ dst,
                      int n8) {   // n8 = elems/8
    int i = blockIdx.x * blockDim.x + threadIdx.x;
    if (i < n8) {
        const float4* p = (const float4*)(src + i * 8);
        float4 v0 = p[0], v1 = p[1];
        __nv_bfloat16 t[8];
        t[0] = __float2bfloat16(v0.x); t[1] = __float2bfloat16(v0.y);
        t[2] = __float2bfloat16(v0.z); t[3] = __float2bfloat16(v0.w);
        t[4] = __float2bfloat16(v1.x); t[5] = __float2bfloat16(v1.y);
        t[6] = __float2bfloat16(v1.z); t[7] = __float2bfloat16(v1.w);
        *(uint4*)(dst + i * 8) = *(uint4*)t;
    }
}

// convert all three weight matrices in one launch
__global__ void k_cvt_w(const float* __restrict__ W0, const float* __restrict__ W1,
                        const float* __restrict__ W2) {
    int i = blockIdx.x * blockDim.x + threadIdx.x;   // 8-elem chunks
    const int c0 = DIN * DH / 8, c1 = DH * DH / 8, c2 = DH * DOUT / 8;
    const float* s; __nv_bfloat16* d; int off;
    if (i < c0) { s = W0; d = g_w0; off = i; }
    else if (i < c0 + c1) { s = W1; d = g_w1; off = i - c0; }
    else if (i < c0 + c1 + c2) { s = W2; d = g_w2; off = i - c0 - c1; }
    else return;
    const float4* p = (const float4*)(s + off * 8);
    float4 v0 = p[0], v1 = p[1];
    __nv_bfloat16 t[8];
    t[0] = __float2bfloat16(v0.x); t[1] = __float2bfloat16(v0.y);
    t[2] = __float2bfloat16(v0.z); t[3] = __float2bfloat16(v0.w);
    t[4] = __float2bfloat16(v1.x); t[5] = __float2bfloat16(v1.y);
    t[6] = __float2bfloat16(v1.z); t[7] = __float2bfloat16(v1.w);
    *(uint4*)(d + off * 8) = *(uint4*)t;
}

// ---------------- CSR construction ----------------
__global__ void k_count(const int* __restrict__ dst, int E) {
    int i = blockIdx.x * blockDim.x + threadIdx.x;
    if (i < E) atomicAdd(&g_deg[dst[i]], 1);
}

__global__ void k_scan_all(int n, int nb) {
    __shared__ int wsum[8];
    __shared__ int s_base;
    const int t = threadIdx.x;
    const int lane = t & 31, w = t >> 5;
    const int base = blockIdx.x * 1024 + t * 4;

    int d0 = (base + 0 < n) ? g_deg[base + 0] : 0;
    int d1 = (base + 1 < n) ? g_deg[base + 1] : 0;
    int d2 = (base + 2 < n) ? g_deg[base + 2] : 0;
    int d3 = (base + 3 < n) ? g_deg[base + 3] : 0;
    if (base + 0 < n) g_dinv[base + 0] = rsqrtf((float)d0 + 1.0f);
    if (base + 1 < n) g_dinv[base + 1] = rsqrtf((float)d1 + 1.0f);
    if (base + 2 < n) g_dinv[base + 2] = rsqrtf((float)d2 + 1.0f);
    if (base + 3 < n) g_dinv[base + 3] = rsqrtf((float)d3 + 1.0f);

    int s0 = d0, s1 = s0 + d1, s2 = s1 + d2, s3 = s2 + d3;
    int ws = s3;
#pragma unroll
    for (int off = 1; off < 32; off <<= 1) {
        int v = __shfl_up_sync(0xFFFFFFFFu, ws, off);
        if (lane >= off) ws += v;
    }
    if (lane == 31) wsum[w] = ws;
    __syncthreads();
    if (w == 0 && lane < 8) {
        int v = wsum[lane];
#pragma unroll
        for (int off = 1; off < 8; off <<= 1) {
            int u = __shfl_up_sync(0x000000FFu, v, off);
            if (lane >= off) v += u;
        }
        wsum[lane] = v;
    }
    __syncthreads();

    if (t == 0) {
        unsigned long long pkt = (((unsigned long long)(unsigned)wsum[7]) << 2) | 1ull;
        atomicExch(&g_state[blockIdx.x], pkt);
    }
    if (w == 0) {
        int sum = 0;
        volatile unsigned long long* st = (volatile unsigned long long*)g_state;
        for (int p0 = (int)blockIdx.x - 1; p0 >= 0; p0 -= 32) {
            int idx = p0 - lane;
            if (idx >= 0) {
                unsigned long long v;
                do { v = st[idx]; } while ((v & 3ull) == 0ull);
                sum += (int)(v >> 2);
            }
        }
#pragma unroll
        for (int off = 16; off > 0; off >>= 1)
            sum += __shfl_xor_sync(0xFFFFFFFFu, sum, off);
        if (lane == 0) s_base = sum;
    }
    __syncthreads();

    const int blk = s_base;
    int wbase = (w == 0) ? 0 : wsum[w - 1];
    int tbase = blk + wbase + ws - s3;
    if (base + 0 < n) { g_offs[base + 0] = tbase;      g_cursor[base + 0] = tbase; }
    if (base + 1 < n) { g_offs[base + 1] = tbase + s0; g_cursor[base + 1] = tbase + s0; }
    if (base + 2 < n) { g_offs[base + 2] = tbase + s1; g_cursor[base + 2] = tbase + s1; }
    if (base + 3 < n) { g_offs[base + 3] = tbase + s2; g_cursor[base + 3] = tbase + s2; }
    if (blockIdx.x == (unsigned)(nb - 1) && t == 255) g_offs[n] = blk + wsum[7];
}

__global__ void k_fill(const int* __restrict__ src, const int* __restrict__ dst, int E) {
    int i = blockIdx.x * blockDim.x + threadIdx.x;
    if (i < E) {
        int d = dst[i];
        int s = src[i];
        int pos = atomicAdd(&g_cursor[d], 1);
        g_edge[pos] = make_int2(s, __float_as_int(g_dinv[s] * g_dinv[d]));
    }
}

// ---------------- bf16 tensor-core GEMM: cp.async double-buffered + ldmatrix ----------------
__device__ __forceinline__ uint32_t smem_u32(const void* p) {
    return (uint32_t)__cvta_generic_to_shared(p);
}

__device__ __forceinline__ void cp16(uint32_t dst, const void* src, int pred) {
    asm volatile("cp.async.cg.shared.global [%0], [%1], 16, %2;"
                 :: "r"(dst), "l"(src), "r"(pred ? 16 : 0));
}

__device__ __forceinline__ void cp_commit() {
    asm volatile("cp.async.commit_group;");
}

__device__ __forceinline__ void ldsm_x4(uint32_t r[4], uint32_t addr) {
    asm volatile("ldmatrix.sync.aligned.m8n8.x4.shared.b16 {%0,%1,%2,%3}, [%4];"
                 : "=r"(r[0]), "=r"(r[1]), "=r"(r[2]), "=r"(r[3]) : "r"(addr));
}

__device__ __forceinline__ void ldsm_x4_t(uint32_t r[4], uint32_t addr) {
    asm volatile("ldmatrix.sync.aligned.m8n8.x4.trans.shared.b16 {%0,%1,%2,%3}, [%4];"
                 : "=r"(r[0]), "=r"(r[1]), "=r"(r[2]), "=r"(r[3]) : "r"(addr));
}

__device__ __forceinline__ void mma_bf16(float c[4], const uint32_t a[4],
                                         uint32_t b0, uint32_t b1) {
    asm volatile(
        "mma.sync.aligned.m16n8k16.row.col.f32.bf16.bf16.f32 "
        "{%0,%1,%2,%3},{%4,%5,%6,%7},{%8,%9},{%0,%1,%2,%3};"
        : "+f"(c[0]), "+f"(c[1]), "+f"(c[2]), "+f"(c[3])
        : "r"(a[0]), "r"(a[1]), "r"(a[2]), "r"(a[3]), "r"(b0), "r"(b1));
}

// BM=64, BK=32, 256 threads = 8 warps (2m x 4n). Warp tile m32 x (F/4).
template <int K, int F>
__global__ void __launch_bounds__(256) k_gemm_bf16(const __nv_bfloat16* __restrict__ A,
                                                   const __nv_bfloat16* __restrict__ Wm,
                                                   __nv_bfloat16* __restrict__ C, int n) {
    constexpr int BM = 64, BK = 32;
    constexpr int AST = 40;        // 80B row stride (16B-aligned, conflict-free for ldmatrix)
    constexpr int WST = F + 8;     // 272B/144B row stride
    constexpr int WNW = F / 4;
    constexpr int NT = WNW / 8;
    constexpr int KT = K / BK;
    constexpr int WCH = F / 8;     // 16B chunks per W row

    __shared__ __align__(16) __nv_bfloat16 As[2][BM * AST];
    __shared__ __align__(16) __nv_bfloat16 Ws[2][BK * WST];

    const int tid = threadIdx.x;
    const int lane = tid & 31;
    const int wid = tid >> 5;
    const int wm = wid >> 2;
    const int wn = wid & 3;
    const int quad = lane >> 3;
    const int lq = lane & 7;
    const int g = lane >> 2;
    const int tg = lane & 3;
    const int row0 = blockIdx.x * BM;

    // staging coords
    const int a_r = tid >> 2;                 // 0..63
    const int a_c = (tid & 3) * 8;            // 0,8,16,24
    const int a_gr = row0 + a_r;
    const int a_ok = a_gr < n;
    const __nv_bfloat16* a_src = A + (size_t)a_gr * K + a_c;

    float acc[2][NT][4];
#pragma unroll
    for (int i = 0; i < 2; i++)
#pragma unroll
        for (int j = 0; j < NT; j++)
#pragma unroll
            for (int q = 0; q < 4; q++) acc[i][j][q] = 0.0f;

    const int a_row = wm * 32 + (quad & 1) * 8 + lq;
    const int a_colq = (quad >> 1) * 8;
    const int b_rowq = (quad & 1) * 8 + lq;
    const int b_col = wn * WNW + (quad >> 1) * 8;

    const uint32_t as0 = smem_u32(As[0]), as1 = smem_u32(As[1]);
    const uint32_t ws0 = smem_u32(Ws[0]), ws1 = smem_u32(Ws[1]);

    // issue loads for tile kt into buffer buf
    auto load_tile = [&](int kt, int buf) {
        const uint32_t asb = buf ? as1 : as0;
        const uint32_t wsb = buf ? ws1 : ws0;
        const int k0 = kt * BK;
        cp16(asb + (a_r * AST + a_c) * 2, a_src + k0, a_ok);
#pragma unroll
        for (int q = 0; q < (BK * WCH) / 256; q++) {
            int idx = tid + q * 256;
            int k = idx / WCH;
            int c8 = (idx % WCH) * 8;
            cp16(wsb + (k * WST + c8) * 2, Wm + (size_t)(k0 + k) * F + c8, 1);
        }
    };

    load_tile(0, 0);
    cp_commit();

#pragma unroll
    for (int kt = 0; kt < KT; kt++) {
        const int cur = kt & 1;
        if (kt + 1 < KT) {
            load_tile(kt + 1, cur ^ 1);
            cp_commit();
            asm volatile("cp.async.wait_group 1;");
        } else {
            asm volatile("cp.async.wait_group 0;");
        }
        __syncthreads();

        const uint32_t asb = cur ? as1 : as0;
        const uint32_t wsb = cur ? ws1 : ws0;
#pragma unroll
        for (int kk = 0; kk < BK; kk += 16) {
            uint32_t af[2][4];
#pragma unroll
            for (int i = 0; i < 2; i++)
                ldsm_x4(af[i], asb + ((a_row + i * 16) * AST + kk + a_colq) * 2);

            uint32_t bf[NT][2];
#pragma unroll
            for (int j2 = 0; j2 < NT / 2; j2++) {
                uint32_t r[4];
                ldsm_x4_t(r, wsb + ((kk + b_rowq) * WST + b_col + j2 * 16) * 2);
                bf[2 * j2][0] = r[0]; bf[2 * j2][1] = r[1];
                bf[2 * j2 + 1][0] = r[2]; bf[2 * j2 + 1][1] = r[3];
            }
#pragma unroll
            for (int j = 0; j < NT; j++)
#pragma unroll
                for (int i = 0; i < 2; i++) mma_bf16(acc[i][j], af[i], bf[j][0], bf[j][1]);
        }
        __syncthreads();
    }

#pragma unroll
    for (int i = 0; i < 2; i++) {
        int gr0 = row0 + wm * 32 + i * 16 + g;
#pragma unroll
        for (int j = 0; j < NT; j++) {
            int col = wn * WNW + j * 8 + 2 * tg;
            if (gr0 < n)
                *(__nv_bfloat162*)(C + (size_t)gr0 * F + col) =
                    __floats2bfloat162_rn(acc[i][j][0], acc[i][j][1]);
            if (gr0 + 8 < n)
                *(__nv_bfloat162*)(C + (size_t)(gr0 + 8) * F + col) =
                    __floats2bfloat162_rn(acc[i][j][2], acc[i][j][3]);
        }
    }
}

// ---------------- aggregation ----------------
__device__ __forceinline__ void fma_bf16x4(float4& acc, uint2 v, float nm) {
    float2 lo = __bfloat1622float2(*(const __nv_bfloat162*)&v.x);
    float2 hi = __bfloat1622float2(*(const __nv_bfloat162*)&v.y);
    acc.x = fmaf(lo.x, nm, acc.x);
    acc.y = fmaf(lo.y, nm, acc.y);
    acc.z = fmaf(hi.x, nm, acc.z);
    acc.w = fmaf(hi.y, nm, acc.w);
}

__global__ void k_agg128(const __nv_bfloat16* __restrict__ h, const float* __restrict__ b,
                         __nv_bfloat16* __restrict__ out, int n) {
    int gw = (blockIdx.x * blockDim.x + threadIdx.x) >> 5;
    int lane = threadIdx.x & 31;
    if (gw >= n) return;

    float4 acc = make_float4(0.f, 0.f, 0.f, 0.f);
    const int beg = g_offs[gw];
    const int end = g_offs[gw + 1];

    int e = beg;
    for (; e + 1 < end; e += 2) {
        int2 e0 = g_edge[e];
        int2 e1 = g_edge[e + 1];
        uint2 v0 = *(const uint2*)(h + (size_t)e0.x * 128 + lane * 4);
        uint2 v1 = *(const uint2*)(h + (size_t)e1.x * 128 + lane * 4);
        fma_bf16x4(acc, v0, __int_as_float(e0.y));
        fma_bf16x4(acc, v1, __int_as_float(e1.y));
    }
    if (e < end) {
        int2 e0 = g_edge[e];
        uint2 v0 = *(const uint2*)(h + (size_t)e0.x * 128 + lane * 4);
        fma_bf16x4(acc, v0, __int_as_float(e0.y));
    }
    {
        float di = g_dinv[gw];
        uint2 v = *(const uint2*)(h + (size_t)gw * 128 + lane * 4);
        fma_bf16x4(acc, v, di * di);
    }
    float4 bv = *(const float4*)(b + lane * 4);
    acc.x = fmaxf(acc.x + bv.x, 0.f);
    acc.y = fmaxf(acc.y + bv.y, 0.f);
    acc.z = fmaxf(acc.z + bv.z, 0.f);
    acc.w = fmaxf(acc.w + bv.w, 0.f);
    uint2 o;
    *(__nv_bfloat162*)&o.x = __floats2bfloat162_rn(acc.x, acc.y);
    *(__nv_bfloat162*)&o.y = __floats2bfloat162_rn(acc.z, acc.w);
    *(uint2*)(out + (size_t)gw * 128 + lane * 4) = o;
}

__global__ void k_agg64_lsm(const __nv_bfloat16* __restrict__ h, const float* __restrict__ b,
                            float* __restrict__ out, int n) {
    int gw = (blockIdx.x * blockDim.x + threadIdx.x) >> 5;
    int lane = threadIdx.x & 31;
    if (gw >= n) return;

    float2 acc = make_float2(0.f, 0.f);
    const int beg = g_offs[gw];
    const int end = g_offs[gw + 1];

    int e = beg;
    for (; e + 1 < end; e += 2) {
        int2 e0 = g_edge[e];
        int2 e1 = g_edge[e + 1];
        uint32_t v0 = *(const uint32_t*)(h + (size_t)e0.x * 64 + lane * 2);
        uint32_t v1 = *(const uint32_t*)(h + (size_t)e1.x * 64 + lane * 2);
        float2 f0 = __bfloat1622float2(*(const __nv_bfloat162*)&v0);
        float2 f1 = __bfloat1622float2(*(const __nv_bfloat162*)&v1);
        float n0 = __int_as_float(e0.y), n1 = __int_as_float(e1.y);
        acc.x = fmaf(f0.x, n0, acc.x); acc.y = fmaf(f0.y, n0, acc.y);
        acc.x = fmaf(f1.x, n1, acc.x); acc.y = fmaf(f1.y, n1, acc.y);
    }
    if (e < end) {
        int2 e0 = g_edge[e];
        uint32_t v0 = *(const uint32_t*)(h + (size_t)e0.x * 64 + lane * 2);
        float2 f0 = __bfloat1622float2(*(const __nv_bfloat162*)&v0);
        float n0 = __int_as_float(e0.y);
        acc.x = fmaf(f0.x, n0, acc.x); acc.y = fmaf(f0.y, n0, acc.y);
    }
    {
        float di = g_dinv[gw];
        float sw = di * di;
        uint32_t v = *(const uint32_t*)(h + (size_t)gw * 64 + lane * 2);
        float2 f = __bfloat1622float2(*(const __nv_bfloat162*)&v);
        acc.x = fmaf(f.x, sw, acc.x); acc.y = fmaf(f.y, sw, acc.y);
    }
    float2 bv = *(const float2*)(b + lane * 2);
    acc.x += bv.x;
    acc.y += bv.y;

    float m = fmaxf(acc.x, acc.y);
#pragma unroll
    for (int o = 16; o > 0; o >>= 1) m = fmaxf(m, __shfl_xor_sync(0xFFFFFFFFu, m, o));
    float se = expf(acc.x - m) + expf(acc.y - m);
#pragma unroll
    for (int o = 16; o > 0; o >>= 1) se += __shfl_xor_sync(0xFFFFFFFFu, se, o);
    float ls = m + logf(se);
    *(float2*)(out + (size_t)gw * 64 + lane * 2) = make_float2(acc.x - ls, acc.y - ls);
}

// ---------------- launch ----------------
extern "C" void kernel_launch(void* const* d_in, const int* in_sizes, int n_in,
                              void* d_out, int out_size) {
    const float* x  = (const float*)d_in[0];
    const int* ei   = (const int*)d_in[1];
    const float* W0 = (const float*)d_in[2];
    const float* b0 = (const float*)d_in[3];
    const float* W1 = (const float*)d_in[4];
    const float* b1 = (const float*)d_in[5];
    const float* W2 = (const float*)d_in[6];
    const float* b2 = (const float*)d_in[7];
    float* out = (float*)d_out;

    const int N = in_sizes[0] / DIN;
    const int E = in_sizes[1] / 2;
    const int* src = ei;
    const int* dst = ei + E;

    __nv_bfloat16 *xb_ptr = nullptr, *h_ptr = nullptr, *a_ptr = nullptr;
    __nv_bfloat16 *w0_ptr = nullptr, *w1_ptr = nullptr, *w2_ptr = nullptr;
    int* deg_ptr = nullptr;
    void* st_ptr = nullptr;
    cudaGetSymbolAddress((void**)&xb_ptr, g_xb);
    cudaGetSymbolAddress((void**)&h_ptr, g_h);
    cudaGetSymbolAddress((void**)&a_ptr, g_a);
    cudaGetSymbolAddress((void**)&w0_ptr, g_w0);
    cudaGetSymbolAddress((void**)&w1_ptr, g_w1);
    cudaGetSymbolAddress((void**)&w2_ptr, g_w2);
    cudaGetSymbolAddress((void**)&deg_ptr, g_deg);
    cudaGetSymbolAddress(&st_ptr, g_state);

    const int TB = 256;
    const int nb = (N + 1023) / 1024;

    // conversions (x + all weights)
    {
        int n8 = N * DIN / 8;
        k_cvt<<<(n8 + TB - 1) / TB, TB>>>(x, xb_ptr, n8);
        int wch = (DIN * DH + DH * DH + DH * DOUT) / 8;
        k_cvt_w<<<(wch + TB - 1) / TB, TB>>>(W0, W1, W2);
    }

    // CSR build
    cudaMemsetAsync(deg_ptr, 0, (size_t)N * sizeof(int));
    cudaMemsetAsync(st_ptr, 0, 64 * sizeof(unsigned long long));
    k_count<<<(E + TB - 1) / TB, TB>>>(dst, E);
    k_scan_all<<<nb, 256>>>(N, nb);
    k_fill<<<(E + TB - 1) / TB, TB>>>(src, dst, E);

    const int gemm_grid = (N + 63) / 64;
    const int agg_grid = (N * 32 + TB - 1) / TB;

    // layer 1
    k_gemm_bf16<DIN, DH><<<gemm_grid, 256>>>(xb_ptr, w0_ptr, h_ptr, N);
    k_agg128<<<agg_grid, TB>>>(h_ptr, b0, a_ptr, N);

    // layer 2
    k_gemm_bf16<DH, DH><<<gemm_grid, 256>>>(a_ptr, w1_ptr, h_ptr, N);
    k_agg128<<<agg_grid, TB>>>(h_ptr, b1, a_ptr, N);

    // layer 3 + fused log_softmax
    k_gemm_bf16<DH, DOUT><<<gemm_grid, 256>>>(a_ptr, w2_ptr, h_ptr, N);
    k_agg64_lsm<<<agg_grid, TB>>>(h_ptr, b2, out, N);
}

// round 7
// speedup vs baseline: 1.1412x; 1.1412x over previous
#include <cuda_runtime.h>
#include <cuda_bf16.h>
#include <math.h>
#include <stdint.h>

#define N_NODES 50000
#define E_EDGES 800000
#define DIN 256
#define DH 128
#define DOUT 64

// ---------------- scratch (static device globals; no allocation) ----------------
__device__ __nv_bfloat16 g_xb[(size_t)N_NODES * DIN];
__device__ __nv_bfloat16 g_h[(size_t)N_NODES * DH];
__device__ __nv_bfloat16 g_a[(size_t)N_NODES * DH];
__device__ __nv_bfloat16 g_w0[DIN * DH];
__device__ __nv_bfloat16 g_w1[DH * DH];
__device__ __nv_bfloat16 g_w2[DH * DOUT];
__device__ float g_dinv[N_NODES];
__device__ int   g_deg[N_NODES];
__device__ int   g_offs[N_NODES + 1];
__device__ int   g_cursor[N_NODES];
__device__ int2  g_edge[E_EDGES];
__device__ unsigned long long g_state[64];

// ---------------- host-side stream/event singletons (created once, no device mem) --
struct HxStreams {
    cudaStream_t s2;
    cudaEvent_t ev0, ev1;
    HxStreams() {
        cudaStreamCreateWithFlags(&s2, cudaStreamNonBlocking);
        cudaEventCreateWithFlags(&ev0, cudaEventDisableTiming);
        cudaEventCreateWithFlags(&ev1, cudaEventDisableTiming);
    }
};
static HxStreams g_sx;

// ---------------- conversions ----------------
__global__ void k_cvt(const float* __restrict__ src, __nv_bfloat16* __restrict__ dst,
                      int n8) {
    int i = blockIdx.x * blockDim.x + threadIdx.x;
    if (i < n8) {
        const float4* p = (const float4*)(src + i * 8);
        float4 v0 = p[0], v1 = p[1];
        __nv_bfloat16 t[8];
        t[0] = __float2bfloat16(v0.x); t[1] = __float2bfloat16(v0.y);
        t[2] = __float2bfloat16(v0.z); t[3] = __float2bfloat16(v0.w);
        t[4] = __float2bfloat16(v1.x); t[5] = __float2bfloat16(v1.y);
        t[6] = __float2bfloat16(v1.z); t[7] = __float2bfloat16(v1.w);
        *(uint4*)(dst + i * 8) = *(uint4*)t;
    }
}

__global__ void k_cvt_w(const float* __restrict__ W0, const float* __restrict__ W1,
                        const float* __restrict__ W2) {
    int i = blockIdx.x * blockDim.x + threadIdx.x;
    const int c0 = DIN * DH / 8, c1 = DH * DH / 8, c2 = DH * DOUT / 8;
    const float* s; __nv_bfloat16* d; int off;
    if (i < c0) { s = W0; d = g_w0; off = i; }
    else if (i < c0 + c1) { s = W1; d = g_w1; off = i - c0; }
    else if (i < c0 + c1 + c2) { s = W2; d = g_w2; off = i - c0 - c1; }
    else return;
    const float4* p = (const float4*)(s + off * 8);
    float4 v0 = p[0], v1 = p[1];
    __nv_bfloat16 t[8];
    t[0] = __float2bfloat16(v0.x); t[1] = __float2bfloat16(v0.y);
    t[2] = __float2bfloat16(v0.z); t[3] = __float2bfloat16(v0.w);
    t[4] = __float2bfloat16(v1.x); t[5] = __float2bfloat16(v1.y);
    t[6] = __float2bfloat16(v1.z); t[7] = __float2bfloat16(v1.w);
    *(uint4*)(d + off * 8) = *(uint4*)t;
}

// ---------------- CSR construction ----------------
__global__ void k_count(const int* __restrict__ dst, int E) {
    int i = blockIdx.x * blockDim.x + threadIdx.x;
    if (i < E) atomicAdd(&g_deg[dst[i]], 1);
}

__global__ void k_scan_all(int n, int nb) {
    __shared__ int wsum[8];
    __shared__ int s_base;
    const int t = threadIdx.x;
    const int lane = t & 31, w = t >> 5;
    const int base = blockIdx.x * 1024 + t * 4;

    int d0 = (base + 0 < n) ? g_deg[base + 0] : 0;
    int d1 = (base + 1 < n) ? g_deg[base + 1] : 0;
    int d2 = (base + 2 < n) ? g_deg[base + 2] : 0;
    int d3 = (base + 3 < n) ? g_deg[base + 3] : 0;
    if (base + 0 < n) g_dinv[base + 0] = rsqrtf((float)d0 + 1.0f);
    if (base + 1 < n) g_dinv[base + 1] = rsqrtf((float)d1 + 1.0f);
    if (base + 2 < n) g_dinv[base + 2] = rsqrtf((float)d2 + 1.0f);
    if (base + 3 < n) g_dinv[base + 3] = rsqrtf((float)d3 + 1.0f);

    int s0 = d0, s1 = s0 + d1, s2 = s1 + d2, s3 = s2 + d3;
    int ws = s3;
#pragma unroll
    for (int off = 1; off < 32; off <<= 1) {
        int v = __shfl_up_sync(0xFFFFFFFFu, ws, off);
        if (lane >= off) ws += v;
    }
    if (lane == 31) wsum[w] = ws;
    __syncthreads();
    if (w == 0 && lane < 8) {
        int v = wsum[lane];
#pragma unroll
        for (int off = 1; off < 8; off <<= 1) {
            int u = __shfl_up_sync(0x000000FFu, v, off);
            if (lane >= off) v += u;
        }
        wsum[lane] = v;
    }
    __syncthreads();

    if (t == 0) {
        unsigned long long pkt = (((unsigned long long)(unsigned)wsum[7]) << 2) | 1ull;
        atomicExch(&g_state[blockIdx.x], pkt);
    }
    if (w == 0) {
        int sum = 0;
        volatile unsigned long long* st = (volatile unsigned long long*)g_state;
        for (int p0 = (int)blockIdx.x - 1; p0 >= 0; p0 -= 32) {
            int idx = p0 - lane;
            if (idx >= 0) {
                unsigned long long v;
                do { v = st[idx]; } while ((v & 3ull) == 0ull);
                sum += (int)(v >> 2);
            }
        }
#pragma unroll
        for (int off = 16; off > 0; off >>= 1)
            sum += __shfl_xor_sync(0xFFFFFFFFu, sum, off);
        if (lane == 0) s_base = sum;
    }
    __syncthreads();

    const int blk = s_base;
    int wbase = (w == 0) ? 0 : wsum[w - 1];
    int tbase = blk + wbase + ws - s3;
    if (base + 0 < n) { g_offs[base + 0] = tbase;      g_cursor[base + 0] = tbase; }
    if (base + 1 < n) { g_offs[base + 1] = tbase + s0; g_cursor[base + 1] = tbase + s0; }
    if (base + 2 < n) { g_offs[base + 2] = tbase + s1; g_cursor[base + 2] = tbase + s1; }
    if (base + 3 < n) { g_offs[base + 3] = tbase + s2; g_cursor[base + 3] = tbase + s2; }
    if (blockIdx.x == (unsigned)(nb - 1) && t == 255) g_offs[n] = blk + wsum[7];
}

__global__ void k_fill(const int* __restrict__ src, const int* __restrict__ dst, int E) {
    int i = blockIdx.x * blockDim.x + threadIdx.x;
    if (i < E) {
        int d = dst[i];
        int s = src[i];
        int pos = atomicAdd(&g_cursor[d], 1);
        g_edge[pos] = make_int2(s, __float_as_int(g_dinv[s] * g_dinv[d]));
    }
}

// ---------------- bf16 GEMM: 3-stage cp.async, BM=128, ldmatrix + mma ----------------
__device__ __forceinline__ uint32_t smem_u32(const void* p) {
    return (uint32_t)__cvta_generic_to_shared(p);
}
__device__ __forceinline__ void cp16(uint32_t dst, const void* src, int pred) {
    asm volatile("cp.async.cg.shared.global [%0], [%1], 16, %2;"
                 :: "r"(dst), "l"(src), "r"(pred ? 16 : 0));
}
__device__ __forceinline__ void cp_commit() {
    asm volatile("cp.async.commit_group;");
}
__device__ __forceinline__ void ldsm_x4(uint32_t r[4], uint32_t addr) {
    asm volatile("ldmatrix.sync.aligned.m8n8.x4.shared.b16 {%0,%1,%2,%3}, [%4];"
                 : "=r"(r[0]), "=r"(r[1]), "=r"(r[2]), "=r"(r[3]) : "r"(addr));
}
__device__ __forceinline__ void ldsm_x4_t(uint32_t r[4], uint32_t addr) {
    asm volatile("ldmatrix.sync.aligned.m8n8.x4.trans.shared.b16 {%0,%1,%2,%3}, [%4];"
                 : "=r"(r[0]), "=r"(r[1]), "=r"(r[2]), "=r"(r[3]) : "r"(addr));
}
__device__ __forceinline__ void mma_bf16(float c[4], const uint32_t a[4],
                                         uint32_t b0, uint32_t b1) {
    asm volatile(
        "mma.sync.aligned.m16n8k16.row.col.f32.bf16.bf16.f32 "
        "{%0,%1,%2,%3},{%4,%5,%6,%7},{%8,%9},{%0,%1,%2,%3};"
        : "+f"(c[0]), "+f"(c[1]), "+f"(c[2]), "+f"(c[3])
        : "r"(a[0]), "r"(a[1]), "r"(a[2]), "r"(a[3]), "r"(b0), "r"(b1));
}

// BM=128, BK=32, 256 threads = 8 warps (4m x 2n). Warp tile m32 x (F/2).
template <int K, int F>
__global__ void __launch_bounds__(256) k_gemm_bf16(const __nv_bfloat16* __restrict__ A,
                                                   const __nv_bfloat16* __restrict__ Wm,
                                                   __nv_bfloat16* __restrict__ C, int n) {
    constexpr int BM = 128, BK = 32, S = 3;
    constexpr int AST = 40;
    constexpr int WST = F + 8;
    constexpr int WM = 4, WN = 2;
    constexpr int WNW = F / WN;        // 64 (F=128) or 32 (F=64)
    constexpr int NT = WNW / 8;        // 8 or 4
    constexpr int KT = K / BK;
    constexpr int WCH = F / 8;         // 16B chunks per W row
    constexpr int ACH = BM / 64;       // A chunks per thread (2)
    constexpr int WQN = (BK * WCH + 255) / 256;  // W chunks per thread (2 or 1)

    __shared__ __align__(16) __nv_bfloat16 As[S][BM * AST];
    __shared__ __align__(16) __nv_bfloat16 Ws[S][BK * WST];

    const int tid = threadIdx.x;
    const int lane = tid & 31;
    const int wid = tid >> 5;
    const int wm = wid >> 1;           // 0..3
    const int wn = wid & 1;            // 0..1
    const int quad = lane >> 3;
    const int lq = lane & 7;
    const int g = lane >> 2;
    const int tg = lane & 3;
    const int row0 = blockIdx.x * BM;

    // staging coords
    int a_soff[ACH]; const __nv_bfloat16* a_src[ACH]; int a_ok[ACH];
#pragma unroll
    for (int q = 0; q < ACH; q++) {
        int idx = tid + q * 256;
        int r = idx >> 2, c = (idx & 3) * 8;
        int gr = row0 + r;
        a_ok[q] = gr < n;
        a_src[q] = A + (size_t)gr * K + c;
        a_soff[q] = (r * AST + c) * 2;
    }
    int w_soff[WQN]; const __nv_bfloat16* w_src[WQN]; int w_ok[WQN];
#pragma unroll
    for (int q = 0; q < WQN; q++) {
        int idx = tid + q * 256;
        int k = idx / WCH, c8 = (idx % WCH) * 8;
        w_ok[q] = idx < BK * WCH;
        w_src[q] = Wm + (size_t)k * F + c8;
        w_soff[q] = (k * WST + c8) * 2;
    }

    float acc[2][NT][4];
#pragma unroll
    for (int i = 0; i < 2; i++)
#pragma unroll
        for (int j = 0; j < NT; j++)
#pragma unroll
            for (int q = 0; q < 4; q++) acc[i][j][q] = 0.0f;

    const int a_row = wm * 32 + (quad & 1) * 8 + lq;
    const int a_colq = (quad >> 1) * 8;
    const int b_rowq = (quad & 1) * 8 + lq;
    const int b_col = wn * WNW + (quad >> 1) * 8;

    const uint32_t as_base = smem_u32(As);
    const uint32_t ws_base = smem_u32(Ws);
    constexpr int ASZ = BM * AST * 2;
    constexpr int WSZ = BK * WST * 2;

    auto load_tile = [&](int kt, int s) {
        const uint32_t asb = as_base + s * ASZ;
        const uint32_t wsb = ws_base + s * WSZ;
        const int k0 = kt * BK;
#pragma unroll
        for (int q = 0; q < ACH; q++)
            cp16(asb + a_soff[q], a_src[q] + k0, a_ok[q]);
#pragma unroll
        for (int q = 0; q < WQN; q++)
            cp16(wsb + w_soff[q], w_src[q] + (size_t)k0 * F, w_ok[q]);
    };

    // prologue: stages 0..S-2
#pragma unroll
    for (int s = 0; s < S - 1; s++) {
        if (s < KT) load_tile(s, s);
        cp_commit();
    }

    for (int kt = 0; kt < KT; kt++) {
        asm volatile("cp.async.wait_group %0;" :: "n"(S - 2));
        __syncthreads();
        // issue tile kt+S-1 into the slot tile kt-1 used (everyone is past it)
        {
            int nxt = kt + S - 1;
            if (nxt < KT) load_tile(nxt, nxt % S);
            cp_commit();
        }
        const int cur = kt % S;
        const uint32_t asb = as_base + cur * ASZ;
        const uint32_t wsb = ws_base + cur * WSZ;
#pragma unroll
        for (int kk = 0; kk < BK; kk += 16) {
            uint32_t af[2][4];
#pragma unroll
            for (int i = 0; i < 2; i++)
                ldsm_x4(af[i], asb + ((a_row + i * 16) * AST + kk + a_colq) * 2);

            uint32_t bf[NT][2];
#pragma unroll
            for (int j2 = 0; j2 < NT / 2; j2++) {
                uint32_t r[4];
                ldsm_x4_t(r, wsb + ((kk + b_rowq) * WST + b_col + j2 * 16) * 2);
                bf[2 * j2][0] = r[0]; bf[2 * j2][1] = r[1];
                bf[2 * j2 + 1][0] = r[2]; bf[2 * j2 + 1][1] = r[3];
            }
#pragma unroll
            for (int j = 0; j < NT; j++)
#pragma unroll
                for (int i = 0; i < 2; i++) mma_bf16(acc[i][j], af[i], bf[j][0], bf[j][1]);
        }
    }

#pragma unroll
    for (int i = 0; i < 2; i++) {
        int gr0 = row0 + wm * 32 + i * 16 + g;
#pragma unroll
        for (int j = 0; j < NT; j++) {
            int col = wn * WNW + j * 8 + 2 * tg;
            if (gr0 < n)
                *(__nv_bfloat162*)(C + (size_t)gr0 * F + col) =
                    __floats2bfloat162_rn(acc[i][j][0], acc[i][j][1]);
            if (gr0 + 8 < n)
                *(__nv_bfloat162*)(C + (size_t)(gr0 + 8) * F + col) =
                    __floats2bfloat162_rn(acc[i][j][2], acc[i][j][3]);
        }
    }
}

// ---------------- aggregation ----------------
__device__ __forceinline__ void fma_bf16x4(float4& acc, uint2 v, float nm) {
    float2 lo = __bfloat1622float2(*(const __nv_bfloat162*)&v.x);
    float2 hi = __bfloat1622float2(*(const __nv_bfloat162*)&v.y);
    acc.x = fmaf(lo.x, nm, acc.x);
    acc.y = fmaf(lo.y, nm, acc.y);
    acc.z = fmaf(hi.x, nm, acc.z);
    acc.w = fmaf(hi.y, nm, acc.w);
}

__global__ void k_agg128(const __nv_bfloat16* __restrict__ h, const float* __restrict__ b,
                         __nv_bfloat16* __restrict__ out, int n) {
    int gw = (blockIdx.x * blockDim.x + threadIdx.x) >> 5;
    int lane = threadIdx.x & 31;
    if (gw >= n) return;

    float4 acc = make_float4(0.f, 0.f, 0.f, 0.f);
    const int beg = g_offs[gw];
    const int end = g_offs[gw + 1];

    int e = beg;
    for (; e + 1 < end; e += 2) {
        int2 e0 = g_edge[e];
        int2 e1 = g_edge[e + 1];
        uint2 v0 = *(const uint2*)(h + (size_t)e0.x * 128 + lane * 4);
        uint2 v1 = *(const uint2*)(h + (size_t)e1.x * 128 + lane * 4);
        fma_bf16x4(acc, v0, __int_as_float(e0.y));
        fma_bf16x4(acc, v1, __int_as_float(e1.y));
    }
    if (e < end) {
        int2 e0 = g_edge[e];
        uint2 v0 = *(const uint2*)(h + (size_t)e0.x * 128 + lane * 4);
        fma_bf16x4(acc, v0, __int_as_float(e0.y));
    }
    {
        float di = g_dinv[gw];
        uint2 v = *(const uint2*)(h + (size_t)gw * 128 + lane * 4);
        fma_bf16x4(acc, v, di * di);
    }
    float4 bv = *(const float4*)(b + lane * 4);
    acc.x = fmaxf(acc.x + bv.x, 0.f);
    acc.y = fmaxf(acc.y + bv.y, 0.f);
    acc.z = fmaxf(acc.z + bv.z, 0.f);
    acc.w = fmaxf(acc.w + bv.w, 0.f);
    uint2 o;
    *(__nv_bfloat162*)&o.x = __floats2bfloat162_rn(acc.x, acc.y);
    *(__nv_bfloat162*)&o.y = __floats2bfloat162_rn(acc.z, acc.w);
    *(uint2*)(out + (size_t)gw * 128 + lane * 4) = o;
}

__global__ void k_agg64_lsm(const __nv_bfloat16* __restrict__ h, const float* __restrict__ b,
                            float* __restrict__ out, int n) {
    int gw = (blockIdx.x * blockDim.x + threadIdx.x) >> 5;
    int lane = threadIdx.x & 31;
    if (gw >= n) return;

    float2 acc = make_float2(0.f, 0.f);
    const int beg = g_offs[gw];
    const int end = g_offs[gw + 1];

    int e = beg;
    for (; e + 1 < end; e += 2) {
        int2 e0 = g_edge[e];
        int2 e1 = g_edge[e + 1];
        uint32_t v0 = *(const uint32_t*)(h + (size_t)e0.x * 64 + lane * 2);
        uint32_t v1 = *(const uint32_t*)(h + (size_t)e1.x * 64 + lane * 2);
        float2 f0 = __bfloat1622float2(*(const __nv_bfloat162*)&v0);
        float2 f1 = __bfloat1622float2(*(const __nv_bfloat162*)&v1);
        float n0 = __int_as_float(e0.y), n1 = __int_as_float(e1.y);
        acc.x = fmaf(f0.x, n0, acc.x); acc.y = fmaf(f0.y, n0, acc.y);
        acc.x = fmaf(f1.x, n1, acc.x); acc.y = fmaf(f1.y, n1, acc.y);
    }
    if (e < end) {
        int2 e0 = g_edge[e];
        uint32_t v0 = *(const uint32_t*)(h + (size_t)e0.x * 64 + lane * 2);
        float2 f0 = __bfloat1622float2(*(const __nv_bfloat162*)&v0);
        float n0 = __int_as_float(e0.y);
        acc.x = fmaf(f0.x, n0, acc.x); acc.y = fmaf(f0.y, n0, acc.y);
    }
    {
        float di = g_dinv[gw];
        float sw = di * di;
        uint32_t v = *(const uint32_t*)(h + (size_t)gw * 64 + lane * 2);
        float2 f = __bfloat1622float2(*(const __nv_bfloat162*)&v);
        acc.x = fmaf(f.x, sw, acc.x); acc.y = fmaf(f.y, sw, acc.y);
    }
    float2 bv = *(const float2*)(b + lane * 2);
    acc.x += bv.x;
    acc.y += bv.y;

    float m = fmaxf(acc.x, acc.y);
#pragma unroll
    for (int o = 16; o > 0; o >>= 1) m = fmaxf(m, __shfl_xor_sync(0xFFFFFFFFu, m, o));
    float se = expf(acc.x - m) + expf(acc.y - m);
#pragma unroll
    for (int o = 16; o > 0; o >>= 1) se += __shfl_xor_sync(0xFFFFFFFFu, se, o);
    float ls = m + logf(se);
    *(float2*)(out + (size_t)gw * 64 + lane * 2) = make_float2(acc.x - ls, acc.y - ls);
}

// ---------------- launch ----------------
extern "C" void kernel_launch(void* const* d_in, const int* in_sizes, int n_in,
                              void* d_out, int out_size) {
    const float* x  = (const float*)d_in[0];
    const int* ei   = (const int*)d_in[1];
    const float* W0 = (const float*)d_in[2];
    const float* b0 = (const float*)d_in[3];
    const float* W1 = (const float*)d_in[4];
    const float* b1 = (const float*)d_in[5];
    const float* W2 = (const float*)d_in[6];
    const float* b2 = (const float*)d_in[7];
    float* out = (float*)d_out;

    const int N = in_sizes[0] / DIN;
    const int E = in_sizes[1] / 2;
    const int* src = ei;
    const int* dst = ei + E;

    __nv_bfloat16 *xb_ptr = nullptr, *h_ptr = nullptr, *a_ptr = nullptr;
    __nv_bfloat16 *w0_ptr = nullptr, *w1_ptr = nullptr, *w2_ptr = nullptr;
    int* deg_ptr = nullptr;
    void* st_ptr = nullptr;
    cudaGetSymbolAddress((void**)&xb_ptr, g_xb);
    cudaGetSymbolAddress((void**)&h_ptr, g_h);
    cudaGetSymbolAddress((void**)&a_ptr, g_a);
    cudaGetSymbolAddress((void**)&w0_ptr, g_w0);
    cudaGetSymbolAddress((void**)&w1_ptr, g_w1);
    cudaGetSymbolAddress((void**)&w2_ptr, g_w2);
    cudaGetSymbolAddress((void**)&deg_ptr, g_deg);
    cudaGetSymbolAddress(&st_ptr, g_state);

    const int TB = 256;
    const int nb = (N + 1023) / 1024;

    // ---- fork: CSR build on side stream ----
    cudaEventRecord(g_sx.ev0, 0);
    cudaStreamWaitEvent(g_sx.s2, g_sx.ev0, 0);
    cudaMemsetAsync(deg_ptr, 0, (size_t)N * sizeof(int), g_sx.s2);
    cudaMemsetAsync(st_ptr, 0, 64 * sizeof(unsigned long long), g_sx.s2);
    k_count<<<(E + TB - 1) / TB, TB, 0, g_sx.s2>>>(dst, E);
    k_scan_all<<<nb, 256, 0, g_sx.s2>>>(N, nb);
    k_fill<<<(E + TB - 1) / TB, TB, 0, g_sx.s2>>>(src, dst, E);
    cudaEventRecord(g_sx.ev1, g_sx.s2);

    // ---- main stream: converts + GEMM1 (independent of CSR) ----
    {
        int n8 = N * DIN / 8;
        k_cvt<<<(n8 + TB - 1) / TB, TB>>>(x, xb_ptr, n8);
        int wch = (DIN * DH + DH * DH + DH * DOUT) / 8;
        k_cvt_w<<<(wch + TB - 1) / TB, TB>>>(W0, W1, W2);
    }

    const int gemm_grid = (N + 127) / 128;
    const int agg_grid = (N * 32 + TB - 1) / TB;

    k_gemm_bf16<DIN, DH><<<gemm_grid, 256>>>(xb_ptr, w0_ptr, h_ptr, N);

    // ---- join: agg needs CSR ----
    cudaStreamWaitEvent(0, g_sx.ev1, 0);

    k_agg128<<<agg_grid, TB>>>(h_ptr, b0, a_ptr, N);

    k_gemm_bf16<DH, DH><<<gemm_grid, 256>>>(a_ptr, w1_ptr, h_ptr, N);
    k_agg128<<<agg_grid, TB>>>(h_ptr, b1, a_ptr, N);

    k_gemm_bf16<DH, DOUT><<<gemm_grid, 256>>>(a_ptr, w2_ptr, h_ptr, N);
    k_agg64_lsm<<<agg_grid, TB>>>(h_ptr, b2, out, N);
}